// round 6
// baseline (speedup 1.0000x reference)
#include <cuda_runtime.h>
#include <cuda_bf16.h>

// Problem: x [32, 512, 512] f32 -> pad 128 each side -> [32, 768, 768]
//          -> nearest-neighbor upsample x4 both dims -> out [32, 3072, 3072] f32.
//
// out[b][i][j] = (512 <= i < 2560 && 512 <= j < 2560)
//               ? x[b][(i-512)/4][(j-512)/4] : 0
//
// Column-tiled version: each thread owns a 4-row x 64B tile of the output —
// exactly the 4 output rows that replicate ONE input row. Interior tiles do a
// single float4 load (each input float4 is loaded exactly once kernel-wide)
// and 16 broadcast float4 streaming stores; pad tiles store 16 zero float4s.
//
// Alignment: PAD*SCALE = 512 -> interior row-quads are r in [128,640),
// interior 64B groups are g in [32,160). No per-lane divergence; each of the
// 16 stores is a fully-coalesced contiguous 2048B warp span.

#define OUT_W          3072
#define OUT_H          3072
#define BATCH          32
#define GROUPS_PER_ROW 192     // 3072 floats / 16 floats per 64B group
#define RQUADS         768     // OUT_H / 4 row-quads per image
// total tiles = 32 * 768 * 192 = 4,718,592 ; /256 = 18,432 blocks exactly

__global__ __launch_bounds__(256) void scale_layer_kernel(
    const float* __restrict__ x, float4* __restrict__ out)
{
    unsigned int idx = blockIdx.x * 256u + threadIdx.x;  // tile index

    unsigned int g = idx % GROUPS_PER_ROW;   // 64B group along the row, 0..191
    unsigned int t = idx / GROUPS_PER_ROW;   // 0..24575
    unsigned int b = t / RQUADS;             // batch 0..31
    unsigned int r = t % RQUADS;             // row-quad 0..767

    float4 v0, v1, v2, v3;

    // interior: r in [128,640)  <=>  output rows [512,2560)
    //           g in [ 32,160)  <=>  output cols [512,2560)
    if ((r - 128u) < 512u && (g - 32u) < 128u) {
        unsigned int ii = r - 128u;          // input row   0..511
        unsigned int jj = (g - 32u) << 2;    // input col   0..508, %4==0
        const float4 in = *reinterpret_cast<const float4*>(
            x + ((size_t)b * 512u + ii) * 512u + jj);
        v0 = make_float4(in.x, in.x, in.x, in.x);
        v1 = make_float4(in.y, in.y, in.y, in.y);
        v2 = make_float4(in.z, in.z, in.z, in.z);
        v3 = make_float4(in.w, in.w, in.w, in.w);
    } else {
        v0 = v1 = v2 = v3 = make_float4(0.f, 0.f, 0.f, 0.f);
    }

    // output rows 4r .. 4r+3 of image b, group g
    // float4-granularity row pitch = 3072/4 = 768
    float4* o = out + ((size_t)b * OUT_H + 4u * r) * 768u + (size_t)g * 4u;

    #pragma unroll
    for (int k = 0; k < 4; k++) {
        __stcs(o + 0, v0);
        __stcs(o + 1, v1);
        __stcs(o + 2, v2);
        __stcs(o + 3, v3);
        o += 768;  // next output row
    }
}

extern "C" void kernel_launch(void* const* d_in, const int* in_sizes, int n_in,
                              void* d_out, int out_size)
{
    const float* x = (const float*)d_in[0];
    float4* out = (float4*)d_out;

    const unsigned int n_tiles =
        (unsigned int)BATCH * RQUADS * GROUPS_PER_ROW;   // 4,718,592
    dim3 grid(n_tiles / 256u);                            // 18,432 blocks
    scale_layer_kernel<<<grid, 256>>>(x, out);
}

// round 8
// speedup vs baseline: 1.6733x; 1.6733x over previous
#include <cuda_runtime.h>
#include <cuda_bf16.h>
#include <cstdint>

// Problem: x [32, 512, 512] f32 -> pad 128 each side -> [32, 768, 768]
//          -> nearest-neighbor upsample x4 both dims -> out [32, 3072, 3072] f32.
//
// out[b][i][j] = (512 <= i < 2560 && 512 <= j < 2560)
//               ? x[b][(i-512)/4][(j-512)/4] : 0
//
// TMA-store version. The STG/L1tex path measured ~4 TB/s ceiling (L1 pinned
// at ~85% while DRAM sat at ~51% across two STG-based kernels). B300's LTS
// cap (~6300 B/cyc) is path-independent, so we route the 1.21 GB of writes
// through cp.async.bulk (async proxy, bypassing L1/LSU wavefronts):
//
//   - one CTA per output row-quad (the 4 output rows replicating one input row)
//   - CTA builds the 12 KB output row ONCE in SMEM (zeros | 4x-broadcast | zeros)
//   - 4 bulk async stores of the SAME smem buffer to the 4 output rows
//     (row replication = cheap smem re-reads by the TMA engine)
//   - wait only for the smem READS before exit; writes drain asynchronously.

#define THREADS 256
#define RQUADS  768            // 3072 output rows / 4 per image
#define BATCH   32
// grid = 32 * 768 = 24576 CTAs

__global__ __launch_bounds__(THREADS) void scale_layer_kernel(
    const float* __restrict__ x, float* __restrict__ out)
{
    __shared__ __align__(16) float row[3072];   // one 12 KB output row

    unsigned int blk = blockIdx.x;
    unsigned int b = blk / RQUADS;              // image 0..31
    unsigned int r = blk % RQUADS;              // row-quad 0..767

    // interior row-quads: r in [128, 640)  (output rows [512, 2560))
    const bool interior_row = (r - 128u) < 512u;
    const float* xrow = x + ((size_t)b * 512u + (r - 128u)) * 512u; // only deref'd if interior

    // Fill the row: float4 group q (floats 4q..4q+3) broadcasts input scalar
    // x[ii][q-128] when q in [128,640), else zero. 768 groups / 256 threads.
    float4* s4 = reinterpret_cast<float4*>(row);
    #pragma unroll
    for (int k = 0; k < 3; k++) {
        unsigned int q = threadIdx.x + 256u * k;
        float v = 0.f;
        if (interior_row && (q - 128u) < 512u)
            v = xrow[q - 128u];                  // coalesced, each elem read once
        s4[q] = make_float4(v, v, v, v);
    }
    __syncthreads();

    if (threadIdx.x == 0) {
        asm volatile("fence.proxy.async.shared::cta;" ::: "memory");
        uint32_t saddr = (uint32_t)__cvta_generic_to_shared(row);
        float* g = out + ((size_t)b * 3072u + 4u * r) * 3072u;
        #pragma unroll
        for (int k = 0; k < 4; k++) {
            asm volatile(
                "cp.async.bulk.global.shared::cta.bulk_group [%0], [%1], %2;"
                :: "l"(g + (size_t)k * 3072u), "r"(saddr), "n"(12288)
                : "memory");
        }
        asm volatile("cp.async.bulk.commit_group;" ::: "memory");
        // wait only until TMA has READ smem; global writes drain async
        asm volatile("cp.async.bulk.wait_group.read 0;" ::: "memory");
    }
}

extern "C" void kernel_launch(void* const* d_in, const int* in_sizes, int n_in,
                              void* d_out, int out_size)
{
    const float* x = (const float*)d_in[0];
    float* out = (float*)d_out;

    dim3 grid(BATCH * RQUADS);   // 24576 CTAs
    scale_layer_kernel<<<grid, THREADS>>>(x, out);
}